// round 5
// baseline (speedup 1.0000x reference)
#include <cuda_runtime.h>
#include <stdint.h>

// Problem constants (match reference setup)
#define NN 100000          // N_NODES
#define DIM 256            // DIM_ATTEN
#define DIM4 (DIM / 4)     // float4 per node row
#define HASH_BITS 22
#define HASH_SIZE (1u << HASH_BITS)   // 4,194,304 slots x u32 = 16 MB
#define HASH_MASK (HASH_SIZE - 1u)

// Scratch (device globals — no dynamic allocation allowed)
__device__ unsigned int g_hash[HASH_SIZE];   // 0 = empty, else 32-bit fingerprint
__device__ int g_in_deg[NN];
__device__ int g_out_deg[NN];

// ---------------------------------------------------------------------------
// Kernel 1: clear hash table (16 MB) + degree counters.
// Doubles as an L2 prefetch of the hash table for the edge kernel.
// ---------------------------------------------------------------------------
__global__ void clear_kernel() {
    const unsigned tid = blockIdx.x * blockDim.x + threadIdx.x;
    const unsigned stride = gridDim.x * blockDim.x;
    uint4* h4 = reinterpret_cast<uint4*>(g_hash);
    const unsigned n4 = HASH_SIZE / 4;           // 1,048,576 uint4 stores
    const uint4 z = make_uint4(0u, 0u, 0u, 0u);
    for (unsigned i = tid; i < n4; i += stride) h4[i] = z;
    for (unsigned i = tid; i < NN; i += stride) {
        g_in_deg[i] = 0;
        g_out_deg[i] = 0;
    }
}

// ---------------------------------------------------------------------------
// Kernel 2: dedup edges via fingerprint hash set (CAS-first probing).
// edge_index is INT32 on device. 4 edges/thread for CAS latency overlap.
// ---------------------------------------------------------------------------
__device__ __forceinline__ unsigned long long mix64(unsigned long long h) {
    h ^= h >> 33;
    h *= 0xff51afd7ed558ccdULL;
    h ^= h >> 33;
    h *= 0xc4ceb9fe1a85ec53ULL;
    h ^= h >> 33;
    return h;
}

__device__ __forceinline__ void insert_edge(int s, int d) {
    s = min(max(s, 0), NN - 1);
    d = min(max(d, 0), NN - 1);
    const unsigned long long key =
        (unsigned long long)s * (unsigned long long)NN + (unsigned long long)d;
    const unsigned long long h = mix64(key);
    unsigned slot = (unsigned)h & HASH_MASK;
    unsigned fp = (unsigned)(h >> 32);
    if (fp == 0u) fp = 1u;                       // 0 is the empty sentinel

    while (true) {
        const unsigned prev = atomicCAS(&g_hash[slot], 0u, fp);
        if (prev == 0u) {                        // first occurrence of this pair
            atomicAdd(&g_in_deg[s], 1);          // REDG, fire-and-forget
            atomicAdd(&g_out_deg[d], 1);
            return;
        }
        if (prev == fp) return;                  // duplicate — drop
        slot = (slot + 1) & HASH_MASK;
    }
}

__global__ void edge_kernel(const int* __restrict__ edge_index, int n_edges) {
    const int t = blockIdx.x * blockDim.x + threadIdx.x;
    const int e = t * 4;
    if (e + 3 < n_edges) {
        // n_edges = 1.6M (divisible by 4); rows are 16B-aligned
        const int4 ss = *reinterpret_cast<const int4*>(edge_index + e);
        const int4 dd = *reinterpret_cast<const int4*>(edge_index + n_edges + e);
        insert_edge(ss.x, dd.x);
        insert_edge(ss.y, dd.y);
        insert_edge(ss.z, dd.z);
        insert_edge(ss.w, dd.w);
    } else {
        for (int i = e; i < n_edges; i++)
            insert_edge(edge_index[i], edge_index[n_edges + i]);
    }
}

// ---------------------------------------------------------------------------
// Kernel 3: node_feature = x + in_tbl[in_deg] + out_tbl[out_deg]
// 16 lanes/node, 4 float4/thread (MLP=4 on the x stream). No cache hints on
// streams; tables via __ldg (hot in L1/L2). Tail of d_out zeroed in-grid.
// ---------------------------------------------------------------------------
__global__ void fuse_kernel(const float4* __restrict__ x,
                            const float4* __restrict__ in_tbl,
                            const float4* __restrict__ out_tbl,
                            float4* __restrict__ out,
                            long long out_elems) {
    const unsigned tid = blockIdx.x * blockDim.x + threadIdx.x;
    const unsigned n_feat_thr = (unsigned)NN * 16u;   // 1,600,000

    if (tid < n_feat_thr) {
        const unsigned node = tid >> 4;               // 16 threads per node
        const unsigned col0 = (tid & 15u) * 4u;       // 4 consecutive float4

        int di = g_in_deg[node];                      // broadcast within group
        int dd = g_out_deg[node];
        di = min(max(di, 0), 511);
        dd = min(max(dd, 0), 511);

        const unsigned xbase = node * (unsigned)DIM4 + col0;
        const unsigned ibase = (unsigned)di * DIM4 + col0;
        const unsigned obase = (unsigned)dd * DIM4 + col0;

        float4 xv[4], a[4], b[4];
#pragma unroll
        for (int i = 0; i < 4; i++) xv[i] = x[xbase + i];
#pragma unroll
        for (int i = 0; i < 4; i++) a[i] = __ldg(&in_tbl[ibase + i]);
#pragma unroll
        for (int i = 0; i < 4; i++) b[i] = __ldg(&out_tbl[obase + i]);

#pragma unroll
        for (int i = 0; i < 4; i++) {
            float4 r;
            r.x = xv[i].x + a[i].x + b[i].x;
            r.y = xv[i].y + a[i].y + b[i].y;
            r.z = xv[i].z + a[i].z + b[i].z;
            r.w = xv[i].w + a[i].w + b[i].w;
            out[xbase + i] = r;
        }
    } else {
        // tail zeroing: scalar floats beyond the node_feature region
        const long long base = (long long)NN * DIM;   // 25,600,000
        const long long i = base + (long long)(tid - n_feat_thr);
        if (i < out_elems) reinterpret_cast<float*>(out)[i] = 0.0f;
    }
}

// ---------------------------------------------------------------------------
// Launch
// Inputs (metadata order):
//   0: x                 [100000, 256] float32
//   1: edge_feature      [1600000, 128] float32 (zeros — unused)
//   2: edge_index        [2, 1600000] int32
//   3: in_degree_table   [512, 256] float32
//   4: out_degree_table  [512, 256] float32
// Output: node_feature   [100000, 256] float32 (+ possible attn_bias tail)
// ---------------------------------------------------------------------------
extern "C" void kernel_launch(void* const* d_in, const int* in_sizes, int n_in,
                              void* d_out, int out_size) {
    const float4* x        = (const float4*)d_in[0];
    const int* ei          = (const int*)d_in[2];
    const float4* in_tbl   = (const float4*)d_in[3];
    const float4* out_tbl  = (const float4*)d_in[4];
    float4* out            = (float4*)d_out;

    const int n_edges = in_sizes[2] / 2;

    // 1) clear scratch (16.8 MB) — also prefetches the hash into L2
    clear_kernel<<<4096, 256>>>();

    // 2) dedup + degree count (4 edges per thread, MLP=4 CAS)
    const int n_thr = (n_edges + 3) / 4;
    edge_kernel<<<(n_thr + 255) / 256, 256>>>(ei, n_edges);

    // 3) fused gather-add + tail zero (HBM-bound streaming kernel)
    const long long nf_elems = (long long)NN * DIM;   // 25,600,000
    const unsigned n_feat_thr = (unsigned)NN * 16u;   // 1,600,000
    long long extra = (long long)out_size - nf_elems;
    if (extra < 0) extra = 0;
    const unsigned total_thr = n_feat_thr + (unsigned)extra;
    fuse_kernel<<<(total_thr + 255) / 256, 256>>>(x, in_tbl, out_tbl, out,
                                                  (long long)out_size);
}

// round 6
// speedup vs baseline: 1.1815x; 1.1815x over previous
#include <cuda_runtime.h>
#include <stdint.h>

// Problem constants (match reference setup)
#define NN 100000          // N_NODES
#define DIM 256            // DIM_ATTEN
#define DIM4 (DIM / 4)     // float4 per node row (64)
#define HASH_BITS 22
#define HASH_SIZE (1u << HASH_BITS)   // 4,194,304 slots x u32 = 16 MB
#define HASH_MASK (HASH_SIZE - 1u)

#define TOTAL4 ((unsigned)NN * DIM4)  // 6,400,000 float4 in node_feature
#define FUSE_BLK 256
#define FUSE_PER_BLK (FUSE_BLK * 4)   // 1024 float4 per block
#define FUSE_FEAT_BLOCKS (TOTAL4 / FUSE_PER_BLK)  // 6250 exactly

// Scratch (device globals — no dynamic allocation allowed)
__device__ unsigned int g_hash[HASH_SIZE];   // 0 = empty, else 32-bit fingerprint
__device__ int g_in_deg[NN];
__device__ int g_out_deg[NN];

// ---------------------------------------------------------------------------
// Kernel 1: clear hash table (16 MB) + degree counters.
// Doubles as an L2 prefetch of the hash table for the edge kernel.
// ---------------------------------------------------------------------------
__global__ void clear_kernel() {
    const unsigned tid = blockIdx.x * blockDim.x + threadIdx.x;
    const unsigned stride = gridDim.x * blockDim.x;
    uint4* h4 = reinterpret_cast<uint4*>(g_hash);
    const unsigned n4 = HASH_SIZE / 4;           // 1,048,576 uint4 stores
    const uint4 z = make_uint4(0u, 0u, 0u, 0u);
    for (unsigned i = tid; i < n4; i += stride) h4[i] = z;
    for (unsigned i = tid; i < NN; i += stride) {
        g_in_deg[i] = 0;
        g_out_deg[i] = 0;
    }
}

// ---------------------------------------------------------------------------
// Kernel 2: dedup edges via fingerprint hash set (CAS-first probing).
// edge_index is INT32 on device. 4 edges/thread for CAS latency overlap.
// ---------------------------------------------------------------------------
__device__ __forceinline__ unsigned long long mix64(unsigned long long h) {
    h ^= h >> 33;
    h *= 0xff51afd7ed558ccdULL;
    h ^= h >> 33;
    h *= 0xc4ceb9fe1a85ec53ULL;
    h ^= h >> 33;
    return h;
}

__device__ __forceinline__ void insert_edge(int s, int d) {
    s = min(max(s, 0), NN - 1);
    d = min(max(d, 0), NN - 1);
    const unsigned long long key =
        (unsigned long long)s * (unsigned long long)NN + (unsigned long long)d;
    const unsigned long long h = mix64(key);
    unsigned slot = (unsigned)h & HASH_MASK;
    unsigned fp = (unsigned)(h >> 32);
    if (fp == 0u) fp = 1u;                       // 0 is the empty sentinel

    while (true) {
        const unsigned prev = atomicCAS(&g_hash[slot], 0u, fp);
        if (prev == 0u) {                        // first occurrence of this pair
            atomicAdd(&g_in_deg[s], 1);          // REDG, fire-and-forget
            atomicAdd(&g_out_deg[d], 1);
            return;
        }
        if (prev == fp) return;                  // duplicate — drop
        slot = (slot + 1) & HASH_MASK;
    }
}

__global__ void edge_kernel(const int* __restrict__ edge_index, int n_edges) {
    const int t = blockIdx.x * blockDim.x + threadIdx.x;
    const int e = t * 4;
    if (e + 3 < n_edges) {
        const int4 ss = *reinterpret_cast<const int4*>(edge_index + e);
        const int4 dd = *reinterpret_cast<const int4*>(edge_index + n_edges + e);
        insert_edge(ss.x, dd.x);
        insert_edge(ss.y, dd.y);
        insert_edge(ss.z, dd.z);
        insert_edge(ss.w, dd.w);
    } else {
        for (int i = e; i < n_edges; i++)
            insert_edge(edge_index[i], edge_index[n_edges + i]);
    }
}

// ---------------------------------------------------------------------------
// Kernel 3: node_feature = x + in_tbl[in_deg] + out_tbl[out_deg]
// COALESCED ILP: thread handles idx = blk*1024 + tid + k*256 (k=0..3).
// Every warp load/store instruction covers a contiguous 512B segment;
// 4 independent x-loads in flight per thread (MLP=4).
// Blocks >= FUSE_FEAT_BLOCKS zero the attn_bias tail of d_out.
// ---------------------------------------------------------------------------
__global__ void fuse_kernel(const float4* __restrict__ x,
                            const float4* __restrict__ in_tbl,
                            const float4* __restrict__ out_tbl,
                            float4* __restrict__ out,
                            long long out_elems) {
    const unsigned blk = blockIdx.x;
    if (blk < FUSE_FEAT_BLOCKS) {
        const unsigned base = blk * FUSE_PER_BLK + threadIdx.x;

        unsigned idx[4], node[4], col[4];
        float4 xv[4], a[4], b[4];
#pragma unroll
        for (int k = 0; k < 4; k++) {
            idx[k] = base + k * FUSE_BLK;
            node[k] = idx[k] >> 6;
            col[k]  = idx[k] & 63u;
        }
        // x loads first: 4 independent DRAM streams
#pragma unroll
        for (int k = 0; k < 4; k++) xv[k] = x[idx[k]];

        // degree loads (warp-broadcast, L1/L2-hot) then table gathers
#pragma unroll
        for (int k = 0; k < 4; k++) {
            int di = g_in_deg[node[k]];
            int dd = g_out_deg[node[k]];
            di = min(max(di, 0), 511);
            dd = min(max(dd, 0), 511);
            a[k] = __ldg(&in_tbl[(unsigned)di * DIM4 + col[k]]);
            b[k] = __ldg(&out_tbl[(unsigned)dd * DIM4 + col[k]]);
        }

#pragma unroll
        for (int k = 0; k < 4; k++) {
            float4 r;
            r.x = xv[k].x + a[k].x + b[k].x;
            r.y = xv[k].y + a[k].y + b[k].y;
            r.z = xv[k].z + a[k].z + b[k].z;
            r.w = xv[k].w + a[k].w + b[k].w;
            out[idx[k]] = r;
        }
    } else {
        // tail zeroing: scalar floats beyond the node_feature region
        const long long tail_tid =
            (long long)(blk - FUSE_FEAT_BLOCKS) * FUSE_BLK + threadIdx.x;
        const long long i = (long long)NN * DIM + tail_tid;
        if (i < out_elems) reinterpret_cast<float*>(out)[i] = 0.0f;
    }
}

// ---------------------------------------------------------------------------
// Launch
// Inputs (metadata order):
//   0: x                 [100000, 256] float32
//   1: edge_feature      [1600000, 128] float32 (zeros — unused)
//   2: edge_index        [2, 1600000] int32
//   3: in_degree_table   [512, 256] float32
//   4: out_degree_table  [512, 256] float32
// Output: node_feature   [100000, 256] float32 (+ possible attn_bias tail)
// ---------------------------------------------------------------------------
extern "C" void kernel_launch(void* const* d_in, const int* in_sizes, int n_in,
                              void* d_out, int out_size) {
    const float4* x        = (const float4*)d_in[0];
    const int* ei          = (const int*)d_in[2];
    const float4* in_tbl   = (const float4*)d_in[3];
    const float4* out_tbl  = (const float4*)d_in[4];
    float4* out            = (float4*)d_out;

    const int n_edges = in_sizes[2] / 2;

    // 1) clear scratch (16.8 MB) — also prefetches the hash into L2
    clear_kernel<<<4096, 256>>>();

    // 2) dedup + degree count (4 edges per thread, MLP=4 CAS)
    const int n_thr = (n_edges + 3) / 4;
    edge_kernel<<<(n_thr + 255) / 256, 256>>>(ei, n_edges);

    // 3) fused gather-add + tail zero (HBM-bound streaming kernel)
    const long long nf_elems = (long long)NN * DIM;   // 25,600,000
    long long extra = (long long)out_size - nf_elems;
    if (extra < 0) extra = 0;
    const unsigned tail_blocks = (unsigned)((extra + FUSE_BLK - 1) / FUSE_BLK);
    fuse_kernel<<<FUSE_FEAT_BLOCKS + tail_blocks, FUSE_BLK>>>(
        x, in_tbl, out_tbl, out, (long long)out_size);
}

// round 7
// speedup vs baseline: 1.3890x; 1.1755x over previous
#include <cuda_runtime.h>
#include <stdint.h>

// Problem constants (match reference setup)
#define NN 100000          // N_NODES
#define DIM 256            // DIM_ATTEN
#define DIM4 (DIM / 4)     // float4 per node row (64)
#define HASH_BITS 22
#define HASH_SIZE (1u << HASH_BITS)   // 4,194,304 slots x u32 = 16 MB
#define HASH_MASK (HASH_SIZE - 1u)

#define TOTAL4 ((unsigned)NN * DIM4)  // 6,400,000 float4 in node_feature
#define FUSE_BLK 256
#define FUSE_PER_BLK (FUSE_BLK * 4)   // 1024 float4 per block
#define FUSE_FEAT_BLOCKS (TOTAL4 / FUSE_PER_BLK)  // 6250 exactly

// Scratch (device globals — no dynamic allocation allowed)
__device__ unsigned int g_hash[HASH_SIZE];   // 0 = empty, else 32-bit fingerprint
__device__ int g_in_deg[NN];
__device__ int g_out_deg[NN];

// ---------------------------------------------------------------------------
// Kernel 1: clear hash table (16 MB) + degree counters.
// Doubles as an L2 prefetch of the hash table for the edge kernel.
// ---------------------------------------------------------------------------
__global__ void clear_kernel() {
    const unsigned tid = blockIdx.x * blockDim.x + threadIdx.x;
    const unsigned stride = gridDim.x * blockDim.x;
    uint4* h4 = reinterpret_cast<uint4*>(g_hash);
    const unsigned n4 = HASH_SIZE / 4;           // 1,048,576 uint4 stores
    const uint4 z = make_uint4(0u, 0u, 0u, 0u);
    for (unsigned i = tid; i < n4; i += stride) h4[i] = z;
    for (unsigned i = tid; i < NN; i += stride) {
        g_in_deg[i] = 0;
        g_out_deg[i] = 0;
    }
}

// ---------------------------------------------------------------------------
// Kernel 2: dedup edges via fingerprint hash set (CAS-first probing).
// edge_index is INT32 on device. ONE edge per thread: dedup is latency-bound
// (each insert is a dependent CAS chain), so maximize thread parallelism.
// ---------------------------------------------------------------------------
__device__ __forceinline__ unsigned long long mix64(unsigned long long h) {
    h ^= h >> 33;
    h *= 0xff51afd7ed558ccdULL;
    h ^= h >> 33;
    h *= 0xc4ceb9fe1a85ec53ULL;
    h ^= h >> 33;
    return h;
}

__global__ void edge_kernel(const int* __restrict__ edge_index, int n_edges) {
    const int e = blockIdx.x * blockDim.x + threadIdx.x;
    if (e >= n_edges) return;

    int s = edge_index[e];            // row 0: src (coalesced)
    int d = edge_index[e + n_edges];  // row 1: dst (coalesced)
    s = min(max(s, 0), NN - 1);
    d = min(max(d, 0), NN - 1);

    const unsigned long long key =
        (unsigned long long)s * (unsigned long long)NN + (unsigned long long)d;
    const unsigned long long h = mix64(key);
    unsigned slot = (unsigned)h & HASH_MASK;
    unsigned fp = (unsigned)(h >> 32);
    if (fp == 0u) fp = 1u;                       // 0 is the empty sentinel

    while (true) {
        const unsigned prev = atomicCAS(&g_hash[slot], 0u, fp);
        if (prev == 0u) {                        // first occurrence of this pair
            atomicAdd(&g_in_deg[s], 1);          // REDG, fire-and-forget
            atomicAdd(&g_out_deg[d], 1);
            return;
        }
        if (prev == fp) return;                  // duplicate — drop
        slot = (slot + 1) & HASH_MASK;
    }
}

// ---------------------------------------------------------------------------
// Kernel 3: node_feature = x + in_tbl[in_deg] + out_tbl[out_deg]
// COALESCED ILP: thread handles idx = blk*1024 + tid + k*256 (k=0..3).
// Every warp load/store instruction covers a contiguous 512B segment;
// 4 independent x-loads in flight per thread (MLP=4).
// Blocks >= FUSE_FEAT_BLOCKS zero the attn_bias tail of d_out.
// ---------------------------------------------------------------------------
__global__ void fuse_kernel(const float4* __restrict__ x,
                            const float4* __restrict__ in_tbl,
                            const float4* __restrict__ out_tbl,
                            float4* __restrict__ out,
                            long long out_elems) {
    const unsigned blk = blockIdx.x;
    if (blk < FUSE_FEAT_BLOCKS) {
        const unsigned base = blk * FUSE_PER_BLK + threadIdx.x;

        unsigned idx[4], node[4], col[4];
        float4 xv[4], a[4], b[4];
#pragma unroll
        for (int k = 0; k < 4; k++) {
            idx[k] = base + k * FUSE_BLK;
            node[k] = idx[k] >> 6;
            col[k]  = idx[k] & 63u;
        }
        // x loads first: 4 independent DRAM streams
#pragma unroll
        for (int k = 0; k < 4; k++) xv[k] = x[idx[k]];

        // degree loads (warp-broadcast, L1/L2-hot) then table gathers
#pragma unroll
        for (int k = 0; k < 4; k++) {
            int di = g_in_deg[node[k]];
            int dd = g_out_deg[node[k]];
            di = min(max(di, 0), 511);
            dd = min(max(dd, 0), 511);
            a[k] = __ldg(&in_tbl[(unsigned)di * DIM4 + col[k]]);
            b[k] = __ldg(&out_tbl[(unsigned)dd * DIM4 + col[k]]);
        }

#pragma unroll
        for (int k = 0; k < 4; k++) {
            float4 r;
            r.x = xv[k].x + a[k].x + b[k].x;
            r.y = xv[k].y + a[k].y + b[k].y;
            r.z = xv[k].z + a[k].z + b[k].z;
            r.w = xv[k].w + a[k].w + b[k].w;
            out[idx[k]] = r;
        }
    } else {
        // tail zeroing: scalar floats beyond the node_feature region
        const long long tail_tid =
            (long long)(blk - FUSE_FEAT_BLOCKS) * FUSE_BLK + threadIdx.x;
        const long long i = (long long)NN * DIM + tail_tid;
        if (i < out_elems) reinterpret_cast<float*>(out)[i] = 0.0f;
    }
}

// ---------------------------------------------------------------------------
// Launch
// Inputs (metadata order):
//   0: x                 [100000, 256] float32
//   1: edge_feature      [1600000, 128] float32 (zeros — unused)
//   2: edge_index        [2, 1600000] int32
//   3: in_degree_table   [512, 256] float32
//   4: out_degree_table  [512, 256] float32
// Output: node_feature   [100000, 256] float32 (+ possible attn_bias tail)
// ---------------------------------------------------------------------------
extern "C" void kernel_launch(void* const* d_in, const int* in_sizes, int n_in,
                              void* d_out, int out_size) {
    const float4* x        = (const float4*)d_in[0];
    const int* ei          = (const int*)d_in[2];
    const float4* in_tbl   = (const float4*)d_in[3];
    const float4* out_tbl  = (const float4*)d_in[4];
    float4* out            = (float4*)d_out;

    const int n_edges = in_sizes[2] / 2;

    // 1) clear scratch (16.8 MB) — also prefetches the hash into L2
    clear_kernel<<<4096, 256>>>();

    // 2) dedup + degree count (1 edge per thread — latency-bound)
    edge_kernel<<<(n_edges + 255) / 256, 256>>>(ei, n_edges);

    // 3) fused gather-add + tail zero (HBM-bound streaming kernel)
    const long long nf_elems = (long long)NN * DIM;   // 25,600,000
    long long extra = (long long)out_size - nf_elems;
    if (extra < 0) extra = 0;
    const unsigned tail_blocks = (unsigned)((extra + FUSE_BLK - 1) / FUSE_BLK);
    fuse_kernel<<<FUSE_FEAT_BLOCKS + tail_blocks, FUSE_BLK>>>(
        x, in_tbl, out_tbl, out, (long long)out_size);
}